// round 12
// baseline (speedup 1.0000x reference)
#include <cuda_runtime.h>
#include <cuda_fp16.h>
#include <math.h>
#include <stdint.h>

#define DIM   512
#define IDIM  1536
#define BATCH 16
#define TLEN  2048
#define MTOT  (BATCH * TLEN)   // 32768

#define STAGES      4
#define STAGE_BYTES 16384      // A tile 8KB + B tile 8KB (128 x 32 halves each)
#define BK          32
#define PGRID       296        // persistent grid: 2 CTAs x 148 SMs

// gemm2 smem extras
#define SC_OFF     (STAGES * STAGE_BYTES)            // 2 x 3KB scale rows
#define TRANS_OFF  (SC_OFF + 2 * 3072)               // 32x132 f32 transpose buf
#define SMEM2      (TRANS_OFF + 32 * 132 * 4)
#define SMEM1      (STAGES * STAGE_BYTES)

// ---------------- scratch (static __device__, no allocations) ----------------
__device__ __half g_y[(size_t)MTOT * DIM];
__device__ __half g_h[(size_t)MTOT * IDIM];
__device__ __half g_w1h[(size_t)IDIM * DIM];
__device__ __half g_w2h[(size_t)DIM * IDIM];
__device__ float  g_part[BATCH * IDIM];
__device__ __half g_scale[BATCH * IDIM];
__device__ float  g_gw2[DIM];
__device__ unsigned g_ctr;

// =============================================================================
// helpers
// =============================================================================
__device__ __forceinline__ float gelu_fast(float v) {
    const float x  = v * 0.70710678118654752f;
    const float ax = fabsf(x);
    const float t  = __fdividef(1.0f, fmaf(0.3275911f, ax, 1.0f));
    float p = fmaf(t, 1.061405429f, -1.453152027f);
    p = fmaf(t, p, 1.421413741f);
    p = fmaf(t, p, -0.284496736f);
    p = fmaf(t, p, 0.254829592f);
    p *= t;
    const float e = __expf(-x * x);
    float erfv = fmaf(-p, e, 1.0f);
    erfv = copysignf(erfv, x);
    return 0.5f * v * (1.0f + erfv);
}
__device__ __forceinline__ uint32_t smem_u32(const void* p) {
    uint32_t a;
    asm("{ .reg .u64 t; cvta.to.shared.u64 t, %1; cvt.u32.u64 %0, t; }"
        : "=r"(a) : "l"(p));
    return a;
}
__device__ __forceinline__ void cp_async16(uint32_t dst, const void* src) {
    asm volatile("cp.async.cg.shared.global [%0], [%1], 16;" :: "r"(dst), "l"(src));
}
#define CP_COMMIT() asm volatile("cp.async.commit_group;" ::: "memory")
#define CP_WAIT(n)  asm volatile("cp.async.wait_group %0;" :: "n"(n) : "memory")

__device__ __forceinline__ void ldsm_x4(uint32_t* d, uint32_t addr) {
    asm volatile("ldmatrix.sync.aligned.m8n8.x4.shared.b16 {%0,%1,%2,%3}, [%4];"
                 : "=r"(d[0]), "=r"(d[1]), "=r"(d[2]), "=r"(d[3]) : "r"(addr));
}
__device__ __forceinline__ uint32_t lds_u32(uint32_t a) {
    uint32_t v;
    asm volatile("ld.shared.b32 %0, [%1];" : "=r"(v) : "r"(a));
    return v;
}
__device__ __forceinline__ uint32_t hmul2(uint32_t a, uint32_t s) {
    uint32_t o;
    asm("mul.rn.f16x2 %0, %1, %2;" : "=r"(o) : "r"(a), "r"(s));
    return o;
}
__device__ __forceinline__ void mma_f16(float* c, const uint32_t* a, const uint32_t* b) {
    asm volatile(
        "mma.sync.aligned.m16n8k16.row.col.f32.f16.f16.f32 "
        "{%0,%1,%2,%3}, {%4,%5,%6,%7}, {%8,%9}, {%0,%1,%2,%3};"
        : "+f"(c[0]), "+f"(c[1]), "+f"(c[2]), "+f"(c[3])
        : "r"(a[0]), "r"(a[1]), "r"(a[2]), "r"(a[3]), "r"(b[0]), "r"(b[1]));
}

__device__ __forceinline__ void issue_stage(
    uint32_t sb, int st, const __half* Ag, const __half* Bg, int kt, int tid, int K)
{
    const uint32_t base = sb + st * STAGE_BYTES;
    #pragma unroll
    for (int q = 0; q < 2; q++) {
        const int cid = tid + q * 256;
        const int r = cid >> 2, c = cid & 3;
        const uint32_t so = (uint32_t)(r * 64 + ((c ^ ((r >> 1) & 3)) << 4));
        cp_async16(base + so,        Ag + (size_t)r * K + kt * BK + c * 8);
        cp_async16(base + 8192 + so, Bg + (size_t)r * K + kt * BK + c * 8);
    }
}

template<bool SCALE>
__device__ __forceinline__ void compute_kiter(
    uint32_t abase, uint32_t bbase,
    uint32_t offA0, const uint32_t* cswA,
    uint32_t offB0, const uint32_t* cswB,
    uint32_t s_addr, float acc[2][8][4])
{
    #pragma unroll
    for (int ks = 0; ks < 2; ks++) {
        uint32_t af[2][4];
        ldsm_x4(af[0], abase + offA0 + cswA[ks]);
        ldsm_x4(af[1], abase + offA0 + 1024 + cswA[ks]);
        if (SCALE) {
            const uint32_t slo = lds_u32(s_addr + ks * 32);
            const uint32_t shi = lds_u32(s_addr + ks * 32 + 16);
            #pragma unroll
            for (int mi = 0; mi < 2; mi++) {
                af[mi][0] = hmul2(af[mi][0], slo);
                af[mi][1] = hmul2(af[mi][1], slo);
                af[mi][2] = hmul2(af[mi][2], shi);
                af[mi][3] = hmul2(af[mi][3], shi);
            }
        }
        uint32_t bf[4][4];
        #pragma unroll
        for (int q = 0; q < 4; q++)
            ldsm_x4(bf[q], bbase + offB0 + q * 1024 + cswB[ks]);
        #pragma unroll
        for (int mi = 0; mi < 2; mi++)
            #pragma unroll
            for (int j = 0; j < 8; j++)
                mma_f16(acc[mi][j], af[mi], &bf[j >> 1][(j & 1) * 2]);
    }
}

struct FragAddr {
    uint32_t offA0, offB0;
    uint32_t cswA[2], cswB[2];
};
__device__ __forceinline__ FragAddr make_frag_addr(int warp, int lane) {
    FragAddr fa;
    const int wm = warp & 3, wn = warp >> 2;
    const int mi4 = lane >> 3, rloc = lane & 7;
    const int rowA = wm * 32 + (mi4 & 1) * 8 + rloc;
    fa.offA0 = rowA * 64;
    const uint32_t rmA = (rowA >> 1) & 3;
    const uint32_t chA = (uint32_t)(mi4 >> 1);
    fa.cswA[0] = ((0 + chA) ^ rmA) << 4;
    fa.cswA[1] = ((2 + chA) ^ rmA) << 4;
    const int rowB = wn * 64 + (mi4 >> 1) * 8 + rloc;
    fa.offB0 = rowB * 64;
    const uint32_t rmB = (rowB >> 1) & 3;
    const uint32_t chB = (uint32_t)(mi4 & 1);
    fa.cswB[0] = ((0 + chB) ^ rmB) << 4;
    fa.cswB[1] = ((2 + chB) ^ rmB) << 4;
    return fa;
}

// =============================================================================
// prep: w1, w2 -> half; zero g_part/g_ctr (blocks 0..767). gw2 (blocks 768..831).
// =============================================================================
__global__ __launch_bounds__(256) void prep_kernel(
    const float* __restrict__ w1, const float* __restrict__ w2,
    const float* __restrict__ grn_b)
{
    const int bid = blockIdx.x;
    const int tid = threadIdx.x;
    if (bid < 768) {
        const int i = bid * 256 + tid;
        {
            const float4 v = *(const float4*)(w1 + (size_t)i * 4);
            *(__half2*)(g_w1h + (size_t)i * 4)     = __floats2half2_rn(v.x, v.y);
            *(__half2*)(g_w1h + (size_t)i * 4 + 2) = __floats2half2_rn(v.z, v.w);
        }
        {
            const float4 v = *(const float4*)(w2 + (size_t)i * 4);
            *(__half2*)(g_w2h + (size_t)i * 4)     = __floats2half2_rn(v.x, v.y);
            *(__half2*)(g_w2h + (size_t)i * 4 + 2) = __floats2half2_rn(v.z, v.w);
        }
        if (i < BATCH * IDIM / 4)
            *(float4*)(g_part + (size_t)i * 4) = make_float4(0.f, 0.f, 0.f, 0.f);
        if (i == 0) g_ctr = 0;
    } else {
        // gw2[c] = grn_b . w2[c,:]  (from FLOAT w2 — independent of halving)
        const int w = (bid - 768) * 8 + (tid >> 5);
        const int lane = tid & 31;
        const float* row = w2 + (size_t)w * IDIM;
        float s = 0.f;
        for (int i = lane; i < IDIM; i += 32) s += row[i] * grn_b[i];
        #pragma unroll
        for (int o = 16; o; o >>= 1) s += __shfl_xor_sync(0xffffffffu, s, o);
        if (lane == 0) g_gw2[w] = s;
    }
}

// =============================================================================
// conv1d depthwise (K=7) + bias + LayerNorm over C; 4 t-outputs per task.
// =============================================================================
__global__ __launch_bounds__(256) void convln_kernel(
    const float* __restrict__ x, const float* __restrict__ dw_w,
    const float* __restrict__ dw_b, const float* __restrict__ ln_g,
    const float* __restrict__ ln_b)
{
    __shared__ float sy[DIM][17];
    const int b  = blockIdx.y;
    const int t0 = blockIdx.x * 16;
    const int tid = threadIdx.x;
    const bool interior = (t0 >= 4) && (t0 + 20 <= TLEN);

    #pragma unroll
    for (int it = 0; it < 8; it++) {
        const int idx = tid + it * 256;     // 0..2047
        const int c = idx >> 2, tq = idx & 3;
        const int tb = t0 + tq * 4 - 3;
        const float* xr = x + ((size_t)b * DIM + c) * TLEN + tb;
        float xv[10];
        if (interior) {
            #pragma unroll
            for (int j = 0; j < 10; j++) xv[j] = xr[j];
        } else {
            #pragma unroll
            for (int j = 0; j < 10; j++) {
                const int t = tb + j;
                xv[j] = (t >= 0 && t < TLEN) ? xr[j] : 0.f;
            }
        }
        const float* wc = dw_w + c * 7;
        const float bv = dw_b[c];
        float o0 = bv, o1 = bv, o2 = bv, o3 = bv;
        #pragma unroll
        for (int k = 0; k < 7; k++) {
            const float w = wc[k];
            o0 = fmaf(xv[k],     w, o0);
            o1 = fmaf(xv[k + 1], w, o1);
            o2 = fmaf(xv[k + 2], w, o2);
            o3 = fmaf(xv[k + 3], w, o3);
        }
        sy[c][tq * 4 + 0] = o0;
        sy[c][tq * 4 + 1] = o1;
        sy[c][tq * 4 + 2] = o2;
        sy[c][tq * 4 + 3] = o3;
    }
    __syncthreads();

    const int wid = tid >> 5, lane = tid & 31;
    #pragma unroll
    for (int rr = 0; rr < 2; rr++) {
        const int tl = wid + rr * 8;
        float sum = 0.f, sq = 0.f;
        #pragma unroll
        for (int c = lane; c < DIM; c += 32) {
            const float v = sy[c][tl];
            sum += v; sq += v * v;
        }
        #pragma unroll
        for (int o = 16; o; o >>= 1) {
            sum += __shfl_xor_sync(0xffffffffu, sum, o);
            sq  += __shfl_xor_sync(0xffffffffu, sq,  o);
        }
        const float mu  = sum * (1.f / DIM);
        const float var = sq * (1.f / DIM) - mu * mu;
        const float rs  = rsqrtf(var + 1e-6f);
        __half* yr = g_y + ((size_t)b * TLEN + (t0 + tl)) * DIM;
        for (int c = lane; c < DIM; c += 32)
            yr[c] = __float2half_rn((sy[c][tl] - mu) * rs * ln_g[c] + ln_b[c]);
    }
}

// =============================================================================
// GEMM1 (persistent): h = gelu(y @ w1^T + b1) + GRN sumsq; last CTA -> g_scale
// =============================================================================
__global__ void __launch_bounds__(256, 2) gemm1_kernel(
    const float* __restrict__ b1, const float* __restrict__ grn_g)
{
    extern __shared__ char smem[];
    const uint32_t sb = smem_u32(smem);
    const int tid = threadIdx.x;
    const int warp = tid >> 5, lane = tid & 31;
    const int wm = warp & 3, wn = warp >> 2;
    const FragAddr fa = make_frag_addr(warp, lane);
    const int NKT = DIM / BK;                     // 16
    const int NT  = (IDIM / 128) * (MTOT / 128);  // 3072
    const int ntile = (NT - (int)blockIdx.x + (int)gridDim.x - 1) / (int)gridDim.x;
    const int total = ntile * NKT;

    int pt = 0, pk = 0;
    const __half *Ap = g_y   + (size_t)(((int)blockIdx.x / 12) * 128) * DIM;
    const __half *Bp = g_w1h + (size_t)(((int)blockIdx.x % 12) * 128) * DIM;

    #pragma unroll
    for (int s = 0; s < STAGES - 1; s++) {
        if (s < total) {
            issue_stage(sb, s & 3, Ap, Bp, pk, tid, DIM);
            if (++pk == NKT) {
                pk = 0; pt++;
                if (pt < ntile) {
                    const int t = (int)blockIdx.x + pt * (int)gridDim.x;
                    Ap = g_y + (size_t)((t / 12) * 128) * DIM;
                    Bp = g_w1h + (size_t)((t % 12) * 128) * DIM;
                }
            }
        }
        CP_COMMIT();
    }

    int ct = 0, kt = 0;
    int m0 = ((int)blockIdx.x / 12) * 128, n0 = ((int)blockIdx.x % 12) * 128;
    float acc[2][8][4] = {};
    const int r4 = lane >> 2, c4 = lane & 3;

    for (int g = 0; g < total; g++) {
        CP_WAIT(STAGES - 2);
        __syncthreads();
        if (g + STAGES - 1 < total) {
            issue_stage(sb, (g + STAGES - 1) & 3, Ap, Bp, pk, tid, DIM);
            if (++pk == NKT) {
                pk = 0; pt++;
                if (pt < ntile) {
                    const int t = (int)blockIdx.x + pt * (int)gridDim.x;
                    Ap = g_y + (size_t)((t / 12) * 128) * DIM;
                    Bp = g_w1h + (size_t)((t % 12) * 128) * DIM;
                }
            }
        }
        CP_COMMIT();
        const uint32_t abase = sb + (g & 3) * STAGE_BYTES;
        compute_kiter<false>(abase, abase + 8192, fa.offA0, fa.cswA, fa.offB0, fa.cswB, 0, acc);

        if (++kt == NKT) {
            kt = 0;
            #pragma unroll
            for (int mi = 0; mi < 2; mi++) {
                #pragma unroll
                for (int j = 0; j < 8; j++) {
                    const int n = n0 + wn * 64 + j * 8 + c4 * 2;
                    const float bv0 = b1[n], bv1 = b1[n + 1];
                    acc[mi][j][0] = __half2float(__float2half_rn(gelu_fast(acc[mi][j][0] + bv0)));
                    acc[mi][j][1] = __half2float(__float2half_rn(gelu_fast(acc[mi][j][1] + bv1)));
                    acc[mi][j][2] = __half2float(__float2half_rn(gelu_fast(acc[mi][j][2] + bv0)));
                    acc[mi][j][3] = __half2float(__float2half_rn(gelu_fast(acc[mi][j][3] + bv1)));
                }
            }
            #pragma unroll
            for (int mi = 0; mi < 2; mi++) {
                const int m = m0 + wm * 32 + mi * 16 + r4;
                #pragma unroll
                for (int j = 0; j < 8; j++) {
                    const int n = n0 + wn * 64 + j * 8 + c4 * 2;
                    *(__half2*)(g_h + (size_t)m * IDIM + n) =
                        __floats2half2_rn(acc[mi][j][0], acc[mi][j][1]);
                    *(__half2*)(g_h + (size_t)(m + 8) * IDIM + n) =
                        __floats2half2_rn(acc[mi][j][2], acc[mi][j][3]);
                }
            }
            const int b = m0 >> 11;
            #pragma unroll
            for (int j = 0; j < 8; j++) {
                float s0 = acc[0][j][0] * acc[0][j][0] + acc[0][j][2] * acc[0][j][2]
                         + acc[1][j][0] * acc[1][j][0] + acc[1][j][2] * acc[1][j][2];
                float s1 = acc[0][j][1] * acc[0][j][1] + acc[0][j][3] * acc[0][j][3]
                         + acc[1][j][1] * acc[1][j][1] + acc[1][j][3] * acc[1][j][3];
                #pragma unroll
                for (int o = 4; o < 32; o <<= 1) {
                    s0 += __shfl_xor_sync(0xffffffffu, s0, o);
                    s1 += __shfl_xor_sync(0xffffffffu, s1, o);
                }
                if (lane < 4) {
                    const int n = n0 + wn * 64 + j * 8 + lane * 2;
                    atomicAdd(&g_part[b * IDIM + n],     s0);
                    atomicAdd(&g_part[b * IDIM + n + 1], s1);
                }
            }
            #pragma unroll
            for (int mi = 0; mi < 2; mi++)
                #pragma unroll
                for (int j = 0; j < 8; j++)
                    #pragma unroll
                    for (int q = 0; q < 4; q++) acc[mi][j][q] = 0.f;
            if (++ct < ntile) {
                const int t = (int)blockIdx.x + ct * (int)gridDim.x;
                m0 = (t / 12) * 128; n0 = (t % 12) * 128;
            }
        }
    }

    // ---- last-CTA GRN scale (one warp per batch x 2 rounds) ----
    __threadfence();
    __shared__ unsigned s_last;
    if (tid == 0) s_last = (atomicAdd(&g_ctr, 1u) == (unsigned)gridDim.x - 1u) ? 1u : 0u;
    __syncthreads();
    if (s_last) {
        #pragma unroll
        for (int rr = 0; rr < 2; rr++) {
            const int b = warp + rr * 8;
            float local = 0.f;
            for (int j = 0; j < IDIM / 32; j++)
                local += sqrtf(g_part[b * IDIM + j * 32 + lane]);
            #pragma unroll
            for (int o = 16; o; o >>= 1) local += __shfl_xor_sync(0xffffffffu, local, o);
            const float inv = 1.f / (local * (1.f / IDIM) + 1e-6f);
            for (int j = 0; j < IDIM / 32; j++) {
                const int i = j * 32 + lane;
                const float gx = sqrtf(g_part[b * IDIM + i]);
                g_scale[b * IDIM + i] = __float2half_rn(grn_g[i] * gx * inv + 1.0f);
            }
        }
    }
}

// =============================================================================
// GEMM2 (persistent, 128x128): out = x + T((h*scale) @ w2^T + gw2 + b2)
// =============================================================================
__global__ void __launch_bounds__(256, 2) gemm2_kernel(
    const float* __restrict__ b2v, const float* __restrict__ xres,
    float* __restrict__ out)
{
    extern __shared__ char smem[];
    const uint32_t sb = smem_u32(smem);
    const int tid = threadIdx.x;
    const int warp = tid >> 5, lane = tid & 31;
    const int wm = warp & 3, wn = warp >> 2;
    const FragAddr fa = make_frag_addr(warp, lane);
    const int NKT = IDIM / BK;                   // 48
    const int NT  = (DIM / 128) * (MTOT / 128);  // 1024
    const int ntile = (NT - (int)blockIdx.x + (int)gridDim.x - 1) / (int)gridDim.x;
    if (ntile <= 0) return;
    const int total = ntile * NKT;

    int pt = 0, pk = 0;
    const __half *Ap, *Bp;
    {
        const int t = (int)blockIdx.x;
        Ap = g_h   + (size_t)((t / 4) * 128) * IDIM;
        Bp = g_w2h + (size_t)((t % 4) * 128) * IDIM;
    }
    #pragma unroll
    for (int s = 0; s < STAGES - 1; s++) {
        if (s < total) {
            if (pk == 0 && tid < 192) {
                const int t = (int)blockIdx.x + pt * (int)gridDim.x;
                const int bbp = ((t / 4) * 128) >> 11;
                cp_async16(sb + SC_OFF + (pt & 1) * 3072 + tid * 16,
                           g_scale + (size_t)bbp * IDIM + tid * 8);
            }
            issue_stage(sb, s & 3, Ap, Bp, pk, tid, IDIM);
            if (++pk == NKT) {
                pk = 0; pt++;
                if (pt < ntile) {
                    const int t = (int)blockIdx.x + pt * (int)gridDim.x;
                    Ap = g_h + (size_t)((t / 4) * 128) * IDIM;
                    Bp = g_w2h + (size_t)((t % 4) * 128) * IDIM;
                }
            }
        }
        CP_COMMIT();
    }

    int ct = 0, kt = 0;
    int m0 = (((int)blockIdx.x) / 4) * 128, n0 = (((int)blockIdx.x) % 4) * 128;
    float acc[2][8][4] = {};
    const int r4 = lane >> 2, c4 = lane & 3;

    for (int g = 0; g < total; g++) {
        CP_WAIT(STAGES - 2);
        __syncthreads();
        if (g + STAGES - 1 < total) {
            if (pk == 0 && tid < 192) {
                const int t = (int)blockIdx.x + pt * (int)gridDim.x;
                const int bbp = ((t / 4) * 128) >> 11;
                cp_async16(sb + SC_OFF + (pt & 1) * 3072 + tid * 16,
                           g_scale + (size_t)bbp * IDIM + tid * 8);
            }
            issue_stage(sb, (g + STAGES - 1) & 3, Ap, Bp, pk, tid, IDIM);
            if (++pk == NKT) {
                pk = 0; pt++;
                if (pt < ntile) {
                    const int t = (int)blockIdx.x + pt * (int)gridDim.x;
                    Ap = g_h + (size_t)((t / 4) * 128) * IDIM;
                    Bp = g_w2h + (size_t)((t % 4) * 128) * IDIM;
                }
            }
        }
        CP_COMMIT();
        const uint32_t abase = sb + (g & 3) * STAGE_BYTES;
        const uint32_t s_addr = sb + SC_OFF + (ct & 1) * 3072 + kt * 64 + c4 * 4;
        compute_kiter<true>(abase, abase + 8192, fa.offA0, fa.cswA, fa.offB0, fa.cswB, s_addr, acc);

        if (++kt == NKT) {
            kt = 0;
            const int bb = m0 >> 11;
            const int t0 = m0 & (TLEN - 1);
            float (*trans)[132] = (float(*)[132])(smem + TRANS_OFF);
            __syncthreads();
            #pragma unroll
            for (int q = 0; q < 4; q++) {
                if (wn == (q >> 1)) {
                    const int jb = (q & 1) * 4;
                    #pragma unroll
                    for (int jl = 0; jl < 4; jl++) {
                        const int cl = (jb + jl) * 8 + c4 * 2 - (q & 1) * 32;
                        #pragma unroll
                        for (int mi = 0; mi < 2; mi++) {
                            const int ml = wm * 32 + mi * 16 + r4;
                            trans[cl][ml]         = acc[mi][jb + jl][0];
                            trans[cl + 1][ml]     = acc[mi][jb + jl][1];
                            trans[cl][ml + 8]     = acc[mi][jb + jl][2];
                            trans[cl + 1][ml + 8] = acc[mi][jb + jl][3];
                        }
                    }
                }
                __syncthreads();
                for (int r = tid; r < 32 * 128; r += 256) {
                    const int cl = r >> 7, tl = r & 127;
                    const int c = n0 + 32 * q + cl;
                    const size_t oi = ((size_t)(bb * DIM + c)) * TLEN + t0 + tl;
                    out[oi] = xres[oi] + trans[cl][tl] + b2v[c] + g_gw2[c];
                }
                __syncthreads();
            }
            #pragma unroll
            for (int mi = 0; mi < 2; mi++)
                #pragma unroll
                for (int j = 0; j < 8; j++)
                    #pragma unroll
                    for (int q = 0; q < 4; q++) acc[mi][j][q] = 0.f;
            if (++ct < ntile) {
                const int t = (int)blockIdx.x + ct * (int)gridDim.x;
                m0 = (t / 4) * 128; n0 = (t % 4) * 128;
            }
        }
    }
}

// =============================================================================
// Launch
// =============================================================================
extern "C" void kernel_launch(void* const* d_in, const int* in_sizes, int n_in,
                              void* d_out, int out_size)
{
    const float* x     = (const float*)d_in[0];
    const float* dw_w  = (const float*)d_in[1];
    const float* dw_b  = (const float*)d_in[2];
    const float* ln_g  = (const float*)d_in[3];
    const float* ln_b  = (const float*)d_in[4];
    const float* w1    = (const float*)d_in[5];
    const float* b1    = (const float*)d_in[6];
    const float* grn_g = (const float*)d_in[7];
    const float* grn_b = (const float*)d_in[8];
    const float* w2    = (const float*)d_in[9];
    const float* b2    = (const float*)d_in[10];
    float* out = (float*)d_out;

    cudaFuncSetAttribute(gemm1_kernel, cudaFuncAttributeMaxDynamicSharedMemorySize, SMEM1);
    cudaFuncSetAttribute(gemm2_kernel, cudaFuncAttributeMaxDynamicSharedMemorySize, SMEM2);

    prep_kernel<<<832, 256>>>(w1, w2, grn_b);
    convln_kernel<<<dim3(TLEN / 16, BATCH), 256>>>(x, dw_w, dw_b, ln_g, ln_b);
    gemm1_kernel<<<PGRID, 256, SMEM1>>>(b1, grn_g);
    gemm2_kernel<<<PGRID, 256, SMEM2>>>(b2, x, out);
}

// round 15
// speedup vs baseline: 1.2005x; 1.2005x over previous
// R15: control re-run of the R9 champion (573.0 us). Source is behaviorally
// byte-identical to R9; only comments differ (broker-cache insurance).
#include <cuda_runtime.h>
#include <cuda_fp16.h>
#include <math.h>
#include <stdint.h>

#define DIM   512
#define IDIM  1536
#define BATCH 16
#define TLEN  2048
#define MTOT  (BATCH * TLEN)   // 32768

#define STAGES      4
#define STAGE_BYTES 16384      // A tile 8KB + B tile 8KB (128 x 32 halves each)
#define BK          32
#define PGRID       296        // persistent grid: 2 CTAs x 148 SMs

// gemm2 smem extras
#define SC_OFF     (STAGES * STAGE_BYTES)            // 2 x 3KB scale rows
#define TRANS_OFF  (SC_OFF + 2 * 3072)               // 32x132 f32 transpose buf
#define SMEM2      (TRANS_OFF + 32 * 132 * 4)
#define SMEM1      (STAGES * STAGE_BYTES)

// ---------------- scratch (static __device__, no allocations) ----------------
__device__ __half g_y[(size_t)MTOT * DIM];
__device__ __half g_h[(size_t)MTOT * IDIM];
__device__ __half g_w1h[(size_t)IDIM * DIM];
__device__ __half g_w2h[(size_t)DIM * IDIM];
__device__ float  g_part[BATCH * IDIM];
__device__ __half g_scale[BATCH * IDIM];
__device__ float  g_gw2[DIM];

// =============================================================================
// helpers
// =============================================================================
__device__ __forceinline__ float gelu_fast(float v) {
    const float x  = v * 0.70710678118654752f;
    const float ax = fabsf(x);
    const float t  = __fdividef(1.0f, fmaf(0.3275911f, ax, 1.0f));
    float p = fmaf(t, 1.061405429f, -1.453152027f);
    p = fmaf(t, p, 1.421413741f);
    p = fmaf(t, p, -0.284496736f);
    p = fmaf(t, p, 0.254829592f);
    p *= t;
    const float e = __expf(-x * x);
    float erfv = fmaf(-p, e, 1.0f);
    erfv = copysignf(erfv, x);
    return 0.5f * v * (1.0f + erfv);
}
__device__ __forceinline__ uint32_t smem_u32(const void* p) {
    uint32_t a;
    asm("{ .reg .u64 t; cvta.to.shared.u64 t, %1; cvt.u32.u64 %0, t; }"
        : "=r"(a) : "l"(p));
    return a;
}
__device__ __forceinline__ void cp_async16(uint32_t dst, const void* src) {
    asm volatile("cp.async.cg.shared.global [%0], [%1], 16;" :: "r"(dst), "l"(src));
}
#define CP_COMMIT() asm volatile("cp.async.commit_group;" ::: "memory")
#define CP_WAIT(n)  asm volatile("cp.async.wait_group %0;" :: "n"(n) : "memory")

__device__ __forceinline__ void ldsm_x4(uint32_t* d, uint32_t addr) {
    asm volatile("ldmatrix.sync.aligned.m8n8.x4.shared.b16 {%0,%1,%2,%3}, [%4];"
                 : "=r"(d[0]), "=r"(d[1]), "=r"(d[2]), "=r"(d[3]) : "r"(addr));
}
__device__ __forceinline__ uint32_t lds_u32(uint32_t a) {
    uint32_t v;
    asm volatile("ld.shared.b32 %0, [%1];" : "=r"(v) : "r"(a));
    return v;
}
__device__ __forceinline__ uint32_t hmul2(uint32_t a, uint32_t s) {
    uint32_t o;
    asm("mul.rn.f16x2 %0, %1, %2;" : "=r"(o) : "r"(a), "r"(s));
    return o;
}
__device__ __forceinline__ void mma_f16(float* c, const uint32_t* a, const uint32_t* b) {
    asm volatile(
        "mma.sync.aligned.m16n8k16.row.col.f32.f16.f16.f32 "
        "{%0,%1,%2,%3}, {%4,%5,%6,%7}, {%8,%9}, {%0,%1,%2,%3};"
        : "+f"(c[0]), "+f"(c[1]), "+f"(c[2]), "+f"(c[3])
        : "r"(a[0]), "r"(a[1]), "r"(a[2]), "r"(a[3]), "r"(b[0]), "r"(b[1]));
}

__device__ __forceinline__ void issue_stage(
    uint32_t sb, int st, const __half* Ag, const __half* Bg, int kt, int tid, int K)
{
    const uint32_t base = sb + st * STAGE_BYTES;
    #pragma unroll
    for (int q = 0; q < 2; q++) {
        const int cid = tid + q * 256;
        const int r = cid >> 2, c = cid & 3;
        const uint32_t so = (uint32_t)(r * 64 + ((c ^ ((r >> 1) & 3)) << 4));
        cp_async16(base + so,        Ag + (size_t)r * K + kt * BK + c * 8);
        cp_async16(base + 8192 + so, Bg + (size_t)r * K + kt * BK + c * 8);
    }
}

template<bool SCALE>
__device__ __forceinline__ void compute_kiter(
    uint32_t abase, uint32_t bbase,
    uint32_t offA0, const uint32_t* cswA,
    uint32_t offB0, const uint32_t* cswB,
    uint32_t s_addr, float acc[2][8][4])
{
    #pragma unroll
    for (int ks = 0; ks < 2; ks++) {
        uint32_t af[2][4];
        ldsm_x4(af[0], abase + offA0 + cswA[ks]);
        ldsm_x4(af[1], abase + offA0 + 1024 + cswA[ks]);
        if (SCALE) {
            const uint32_t slo = lds_u32(s_addr + ks * 32);
            const uint32_t shi = lds_u32(s_addr + ks * 32 + 16);
            #pragma unroll
            for (int mi = 0; mi < 2; mi++) {
                af[mi][0] = hmul2(af[mi][0], slo);
                af[mi][1] = hmul2(af[mi][1], slo);
                af[mi][2] = hmul2(af[mi][2], shi);
                af[mi][3] = hmul2(af[mi][3], shi);
            }
        }
        uint32_t bf[4][4];
        #pragma unroll
        for (int q = 0; q < 4; q++)
            ldsm_x4(bf[q], bbase + offB0 + q * 1024 + cswB[ks]);
        #pragma unroll
        for (int mi = 0; mi < 2; mi++)
            #pragma unroll
            for (int j = 0; j < 8; j++)
                mma_f16(acc[mi][j], af[mi], &bf[j >> 1][(j & 1) * 2]);
    }
}

struct FragAddr {
    uint32_t offA0, offB0;
    uint32_t cswA[2], cswB[2];
};
__device__ __forceinline__ FragAddr make_frag_addr(int warp, int lane) {
    FragAddr fa;
    const int wm = warp & 3, wn = warp >> 2;
    const int mi4 = lane >> 3, rloc = lane & 7;
    const int rowA = wm * 32 + (mi4 & 1) * 8 + rloc;
    fa.offA0 = rowA * 64;
    const uint32_t rmA = (rowA >> 1) & 3;
    const uint32_t chA = (uint32_t)(mi4 >> 1);
    fa.cswA[0] = ((0 + chA) ^ rmA) << 4;
    fa.cswA[1] = ((2 + chA) ^ rmA) << 4;
    const int rowB = wn * 64 + (mi4 >> 1) * 8 + rloc;
    fa.offB0 = rowB * 64;
    const uint32_t rmB = (rowB >> 1) & 3;
    const uint32_t chB = (uint32_t)(mi4 & 1);
    fa.cswB[0] = ((0 + chB) ^ rmB) << 4;
    fa.cswB[1] = ((2 + chB) ^ rmB) << 4;
    return fa;
}

// =============================================================================
// prep: w1, w2 -> half; zero g_part (blocks 0..767). gw2 (blocks 768..831).
// =============================================================================
__global__ __launch_bounds__(256) void prep_kernel(
    const float* __restrict__ w1, const float* __restrict__ w2,
    const float* __restrict__ grn_b)
{
    const int bid = blockIdx.x;
    const int tid = threadIdx.x;
    if (bid < 768) {
        const int i = bid * 256 + tid;
        {
            const float4 v = *(const float4*)(w1 + (size_t)i * 4);
            *(__half2*)(g_w1h + (size_t)i * 4)     = __floats2half2_rn(v.x, v.y);
            *(__half2*)(g_w1h + (size_t)i * 4 + 2) = __floats2half2_rn(v.z, v.w);
        }
        {
            const float4 v = *(const float4*)(w2 + (size_t)i * 4);
            *(__half2*)(g_w2h + (size_t)i * 4)     = __floats2half2_rn(v.x, v.y);
            *(__half2*)(g_w2h + (size_t)i * 4 + 2) = __floats2half2_rn(v.z, v.w);
        }
        if (i < BATCH * IDIM / 4)
            *(float4*)(g_part + (size_t)i * 4) = make_float4(0.f, 0.f, 0.f, 0.f);
    } else {
        const int w = (bid - 768) * 8 + (tid >> 5);
        const int lane = tid & 31;
        const float* row = w2 + (size_t)w * IDIM;
        float s = 0.f;
        for (int i = lane; i < IDIM; i += 32) s += row[i] * grn_b[i];
        #pragma unroll
        for (int o = 16; o; o >>= 1) s += __shfl_xor_sync(0xffffffffu, s, o);
        if (lane == 0) g_gw2[w] = s;
    }
}

// =============================================================================
// conv1d depthwise (K=7) + bias + LayerNorm over C; 4 t-outputs per task.
// =============================================================================
__global__ __launch_bounds__(256) void convln_kernel(
    const float* __restrict__ x, const float* __restrict__ dw_w,
    const float* __restrict__ dw_b, const float* __restrict__ ln_g,
    const float* __restrict__ ln_b)
{
    __shared__ float sy[DIM][17];
    const int b  = blockIdx.y;
    const int t0 = blockIdx.x * 16;
    const int tid = threadIdx.x;
    const bool interior = (t0 >= 4) && (t0 + 20 <= TLEN);

    #pragma unroll
    for (int it = 0; it < 8; it++) {
        const int idx = tid + it * 256;
        const int c = idx >> 2, tq = idx & 3;
        const int tb = t0 + tq * 4 - 3;
        const float* xr = x + ((size_t)b * DIM + c) * TLEN + tb;
        float xv[10];
        if (interior) {
            #pragma unroll
            for (int j = 0; j < 10; j++) xv[j] = xr[j];
        } else {
            #pragma unroll
            for (int j = 0; j < 10; j++) {
                const int t = tb + j;
                xv[j] = (t >= 0 && t < TLEN) ? xr[j] : 0.f;
            }
        }
        const float* wc = dw_w + c * 7;
        const float bv = dw_b[c];
        float o0 = bv, o1 = bv, o2 = bv, o3 = bv;
        #pragma unroll
        for (int k = 0; k < 7; k++) {
            const float w = wc[k];
            o0 = fmaf(xv[k],     w, o0);
            o1 = fmaf(xv[k + 1], w, o1);
            o2 = fmaf(xv[k + 2], w, o2);
            o3 = fmaf(xv[k + 3], w, o3);
        }
        sy[c][tq * 4 + 0] = o0;
        sy[c][tq * 4 + 1] = o1;
        sy[c][tq * 4 + 2] = o2;
        sy[c][tq * 4 + 3] = o3;
    }
    __syncthreads();

    const int wid = tid >> 5, lane = tid & 31;
    #pragma unroll
    for (int rr = 0; rr < 2; rr++) {
        const int tl = wid + rr * 8;
        float sum = 0.f, sq = 0.f;
        #pragma unroll
        for (int c = lane; c < DIM; c += 32) {
            const float v = sy[c][tl];
            sum += v; sq += v * v;
        }
        #pragma unroll
        for (int o = 16; o; o >>= 1) {
            sum += __shfl_xor_sync(0xffffffffu, sum, o);
            sq  += __shfl_xor_sync(0xffffffffu, sq,  o);
        }
        const float mu  = sum * (1.f / DIM);
        const float var = sq * (1.f / DIM) - mu * mu;
        const float rs  = rsqrtf(var + 1e-6f);
        __half* yr = g_y + ((size_t)b * TLEN + (t0 + tl)) * DIM;
        for (int c = lane; c < DIM; c += 32)
            yr[c] = __float2half_rn((sy[c][tl] - mu) * rs * ln_g[c] + ln_b[c]);
    }
}

// =============================================================================
// GEMM1 (persistent, continuous pipeline): h = gelu(y @ w1^T + b1) + GRN sumsq
// =============================================================================
__global__ void __launch_bounds__(256, 2) gemm1_kernel(const float* __restrict__ b1)
{
    extern __shared__ char smem[];
    const uint32_t sb = smem_u32(smem);
    const int tid = threadIdx.x;
    const int warp = tid >> 5, lane = tid & 31;
    const int wm = warp & 3, wn = warp >> 2;
    const FragAddr fa = make_frag_addr(warp, lane);
    const int NKT = DIM / BK;                     // 16
    const int NT  = (IDIM / 128) * (MTOT / 128);  // 3072
    const int ntile = (NT - (int)blockIdx.x + (int)gridDim.x - 1) / (int)gridDim.x;
    if (ntile <= 0) return;
    const int total = ntile * NKT;

    int pt = 0, pk = 0;
    const __half *Ap = g_y   + (size_t)(((int)blockIdx.x / 12) * 128) * DIM;
    const __half *Bp = g_w1h + (size_t)(((int)blockIdx.x % 12) * 128) * DIM;

    #pragma unroll
    for (int s = 0; s < STAGES - 1; s++) {
        if (s < total) {
            issue_stage(sb, s & 3, Ap, Bp, pk, tid, DIM);
            if (++pk == NKT) {
                pk = 0; pt++;
                if (pt < ntile) {
                    const int t = (int)blockIdx.x + pt * (int)gridDim.x;
                    Ap = g_y + (size_t)((t / 12) * 128) * DIM;
                    Bp = g_w1h + (size_t)((t % 12) * 128) * DIM;
                }
            }
        }
        CP_COMMIT();
    }

    int ct = 0, kt = 0;
    int m0 = ((int)blockIdx.x / 12) * 128, n0 = ((int)blockIdx.x % 12) * 128;
    float acc[2][8][4] = {};
    const int r4 = lane >> 2, c4 = lane & 3;

    for (int g = 0; g < total; g++) {
        CP_WAIT(STAGES - 2);
        __syncthreads();
        if (g + STAGES - 1 < total) {
            issue_stage(sb, (g + STAGES - 1) & 3, Ap, Bp, pk, tid, DIM);
            if (++pk == NKT) {
                pk = 0; pt++;
                if (pt < ntile) {
                    const int t = (int)blockIdx.x + pt * (int)gridDim.x;
                    Ap = g_y + (size_t)((t / 12) * 128) * DIM;
                    Bp = g_w1h + (size_t)((t % 12) * 128) * DIM;
                }
            }
        }
        CP_COMMIT();
        const uint32_t abase = sb + (g & 3) * STAGE_BYTES;
        compute_kiter<false>(abase, abase + 8192, fa.offA0, fa.cswA, fa.offB0, fa.cswB, 0, acc);

        if (++kt == NKT) {
            kt = 0;
            #pragma unroll
            for (int mi = 0; mi < 2; mi++) {
                #pragma unroll
                for (int j = 0; j < 8; j++) {
                    const int n = n0 + wn * 64 + j * 8 + c4 * 2;
                    const float bv0 = b1[n], bv1 = b1[n + 1];
                    acc[mi][j][0] = __half2float(__float2half_rn(gelu_fast(acc[mi][j][0] + bv0)));
                    acc[mi][j][1] = __half2float(__float2half_rn(gelu_fast(acc[mi][j][1] + bv1)));
                    acc[mi][j][2] = __half2float(__float2half_rn(gelu_fast(acc[mi][j][2] + bv0)));
                    acc[mi][j][3] = __half2float(__float2half_rn(gelu_fast(acc[mi][j][3] + bv1)));
                }
            }
            #pragma unroll
            for (int mi = 0; mi < 2; mi++) {
                const int m = m0 + wm * 32 + mi * 16 + r4;
                #pragma unroll
                for (int j = 0; j < 8; j++) {
                    const int n = n0 + wn * 64 + j * 8 + c4 * 2;
                    *(__half2*)(g_h + (size_t)m * IDIM + n) =
                        __floats2half2_rn(acc[mi][j][0], acc[mi][j][1]);
                    *(__half2*)(g_h + (size_t)(m + 8) * IDIM + n) =
                        __floats2half2_rn(acc[mi][j][2], acc[mi][j][3]);
                }
            }
            const int b = m0 >> 11;
            #pragma unroll
            for (int j = 0; j < 8; j++) {
                float s0 = acc[0][j][0] * acc[0][j][0] + acc[0][j][2] * acc[0][j][2]
                         + acc[1][j][0] * acc[1][j][0] + acc[1][j][2] * acc[1][j][2];
                float s1 = acc[0][j][1] * acc[0][j][1] + acc[0][j][3] * acc[0][j][3]
                         + acc[1][j][1] * acc[1][j][1] + acc[1][j][3] * acc[1][j][3];
                #pragma unroll
                for (int o = 4; o < 32; o <<= 1) {
                    s0 += __shfl_xor_sync(0xffffffffu, s0, o);
                    s1 += __shfl_xor_sync(0xffffffffu, s1, o);
                }
                if (lane < 4) {
                    const int n = n0 + wn * 64 + j * 8 + lane * 2;
                    atomicAdd(&g_part[b * IDIM + n],     s0);
                    atomicAdd(&g_part[b * IDIM + n + 1], s1);
                }
            }
            #pragma unroll
            for (int mi = 0; mi < 2; mi++)
                #pragma unroll
                for (int j = 0; j < 8; j++)
                    #pragma unroll
                    for (int q = 0; q < 4; q++) acc[mi][j][q] = 0.f;
            if (++ct < ntile) {
                const int t = (int)blockIdx.x + ct * (int)gridDim.x;
                m0 = (t / 12) * 128; n0 = (t % 12) * 128;
            }
        }
    }
}

// =============================================================================
// GRN scale (16 blocks)
// =============================================================================
__global__ __launch_bounds__(256) void grn_scale_kernel(const float* __restrict__ grn_g)
{
    __shared__ float sgx[IDIM];
    __shared__ float red[256];
    const int b = blockIdx.x;
    const int tid = threadIdx.x;
    float local = 0.f;
    for (int i = tid; i < IDIM; i += 256) {
        const float gx = sqrtf(g_part[b * IDIM + i]);
        sgx[i] = gx;
        local += gx;
    }
    red[tid] = local;
    __syncthreads();
    for (int o = 128; o; o >>= 1) {
        if (tid < o) red[tid] += red[tid + o];
        __syncthreads();
    }
    const float mean = red[0] * (1.f / IDIM);
    const float inv  = 1.f / (mean + 1e-6f);
    for (int i = tid; i < IDIM; i += 256)
        g_scale[b * IDIM + i] = __float2half_rn(grn_g[i] * sgx[i] * inv + 1.0f);
}

// =============================================================================
// GEMM2 (persistent, continuous pipeline): out = x + T((h*scale) @ w2^T + gw2 + b2)
// =============================================================================
__global__ void __launch_bounds__(256, 2) gemm2_kernel(
    const float* __restrict__ b2v, const float* __restrict__ xres,
    float* __restrict__ out)
{
    extern __shared__ char smem[];
    const uint32_t sb = smem_u32(smem);
    const int tid = threadIdx.x;
    const int warp = tid >> 5, lane = tid & 31;
    const int wm = warp & 3, wn = warp >> 2;
    const FragAddr fa = make_frag_addr(warp, lane);
    const int NKT = IDIM / BK;                   // 48
    const int NT  = (DIM / 128) * (MTOT / 128);  // 1024
    const int ntile = (NT - (int)blockIdx.x + (int)gridDim.x - 1) / (int)gridDim.x;
    if (ntile <= 0) return;
    const int total = ntile * NKT;

    int pt = 0, pk = 0;
    const __half *Ap, *Bp;
    {
        const int t = (int)blockIdx.x;
        Ap = g_h   + (size_t)((t / 4) * 128) * IDIM;
        Bp = g_w2h + (size_t)((t % 4) * 128) * IDIM;
    }
    #pragma unroll
    for (int s = 0; s < STAGES - 1; s++) {
        if (s < total) {
            if (pk == 0 && tid < 192) {
                const int t = (int)blockIdx.x + pt * (int)gridDim.x;
                const int bbp = ((t / 4) * 128) >> 11;
                cp_async16(sb + SC_OFF + (pt & 1) * 3072 + tid * 16,
                           g_scale + (size_t)bbp * IDIM + tid * 8);
            }
            issue_stage(sb, s & 3, Ap, Bp, pk, tid, IDIM);
            if (++pk == NKT) {
                pk = 0; pt++;
                if (pt < ntile) {
                    const int t = (int)blockIdx.x + pt * (int)gridDim.x;
                    Ap = g_h + (size_t)((t / 4) * 128) * IDIM;
                    Bp = g_w2h + (size_t)((t % 4) * 128) * IDIM;
                }
            }
        }
        CP_COMMIT();
    }

    int ct = 0, kt = 0;
    int m0 = (((int)blockIdx.x) / 4) * 128, n0 = (((int)blockIdx.x) % 4) * 128;
    float acc[2][8][4] = {};
    const int r4 = lane >> 2, c4 = lane & 3;

    for (int g = 0; g < total; g++) {
        CP_WAIT(STAGES - 2);
        __syncthreads();
        if (g + STAGES - 1 < total) {
            if (pk == 0 && tid < 192) {
                const int t = (int)blockIdx.x + pt * (int)gridDim.x;
                const int bbp = ((t / 4) * 128) >> 11;
                cp_async16(sb + SC_OFF + (pt & 1) * 3072 + tid * 16,
                           g_scale + (size_t)bbp * IDIM + tid * 8);
            }
            issue_stage(sb, (g + STAGES - 1) & 3, Ap, Bp, pk, tid, IDIM);
            if (++pk == NKT) {
                pk = 0; pt++;
                if (pt < ntile) {
                    const int t = (int)blockIdx.x + pt * (int)gridDim.x;
                    Ap = g_h + (size_t)((t / 4) * 128) * IDIM;
                    Bp = g_w2h + (size_t)((t % 4) * 128) * IDIM;
                }
            }
        }
        CP_COMMIT();
        const uint32_t abase = sb + (g & 3) * STAGE_BYTES;
        const uint32_t s_addr = sb + SC_OFF + (ct & 1) * 3072 + kt * 64 + c4 * 4;
        compute_kiter<true>(abase, abase + 8192, fa.offA0, fa.cswA, fa.offB0, fa.cswB, s_addr, acc);

        if (++kt == NKT) {
            kt = 0;
            const int bb = m0 >> 11;
            const int t0 = m0 & (TLEN - 1);
            float (*trans)[132] = (float(*)[132])(smem + TRANS_OFF);
            __syncthreads();
            #pragma unroll
            for (int q = 0; q < 4; q++) {
                if (wn == (q >> 1)) {
                    const int jb = (q & 1) * 4;
                    #pragma unroll
                    for (int jl = 0; jl < 4; jl++) {
                        const int cl = (jb + jl) * 8 + c4 * 2 - (q & 1) * 32;
                        #pragma unroll
                        for (int mi = 0; mi < 2; mi++) {
                            const int ml = wm * 32 + mi * 16 + r4;
                            trans[cl][ml]         = acc[mi][jb + jl][0];
                            trans[cl + 1][ml]     = acc[mi][jb + jl][1];
                            trans[cl][ml + 8]     = acc[mi][jb + jl][2];
                            trans[cl + 1][ml + 8] = acc[mi][jb + jl][3];
                        }
                    }
                }
                __syncthreads();
                for (int r = tid; r < 32 * 128; r += 256) {
                    const int cl = r >> 7, tl = r & 127;
                    const int c = n0 + 32 * q + cl;
                    const size_t oi = ((size_t)(bb * DIM + c)) * TLEN + t0 + tl;
                    out[oi] = xres[oi] + trans[cl][tl] + b2v[c] + g_gw2[c];
                }
                __syncthreads();
            }
            #pragma unroll
            for (int mi = 0; mi < 2; mi++)
                #pragma unroll
                for (int j = 0; j < 8; j++)
                    #pragma unroll
                    for (int q = 0; q < 4; q++) acc[mi][j][q] = 0.f;
            if (++ct < ntile) {
                const int t = (int)blockIdx.x + ct * (int)gridDim.x;
                m0 = (t / 4) * 128; n0 = (t % 4) * 128;
            }
        }
    }
}

// =============================================================================
// Launch
// =============================================================================
extern "C" void kernel_launch(void* const* d_in, const int* in_sizes, int n_in,
                              void* d_out, int out_size)
{
    const float* x     = (const float*)d_in[0];
    const float* dw_w  = (const float*)d_in[1];
    const float* dw_b  = (const float*)d_in[2];
    const float* ln_g  = (const float*)d_in[3];
    const float* ln_b  = (const float*)d_in[4];
    const float* w1    = (const float*)d_in[5];
    const float* b1    = (const float*)d_in[6];
    const float* grn_g = (const float*)d_in[7];
    const float* grn_b = (const float*)d_in[8];
    const float* w2    = (const float*)d_in[9];
    const float* b2    = (const float*)d_in[10];
    float* out = (float*)d_out;

    cudaFuncSetAttribute(gemm1_kernel, cudaFuncAttributeMaxDynamicSharedMemorySize, SMEM1);
    cudaFuncSetAttribute(gemm2_kernel, cudaFuncAttributeMaxDynamicSharedMemorySize, SMEM2);

    prep_kernel<<<832, 256>>>(w1, w2, grn_b);
    convln_kernel<<<dim3(TLEN / 16, BATCH), 256>>>(x, dw_w, dw_b, ln_g, ln_b);
    gemm1_kernel<<<PGRID, 256, SMEM1>>>(b1);
    grn_scale_kernel<<<16, 256>>>(grn_g);
    gemm2_kernel<<<PGRID, 256, SMEM2>>>(b2, x, out);
}

// round 16
// speedup vs baseline: 1.2347x; 1.0285x over previous
// R16: R15 champion with (a) prep+gw2+convln fused into one pre_kernel and
// (b) conv x-loads vectorized to 4x LDG.128. GEMM/grn kernels byte-identical.
#include <cuda_runtime.h>
#include <cuda_fp16.h>
#include <math.h>
#include <stdint.h>

#define DIM   512
#define IDIM  1536
#define BATCH 16
#define TLEN  2048
#define MTOT  (BATCH * TLEN)   // 32768

#define STAGES      4
#define STAGE_BYTES 16384      // A tile 8KB + B tile 8KB (128 x 32 halves each)
#define BK          32
#define PGRID       296        // persistent grid: 2 CTAs x 148 SMs

// gemm2 smem extras
#define SC_OFF     (STAGES * STAGE_BYTES)            // 2 x 3KB scale rows
#define TRANS_OFF  (SC_OFF + 2 * 3072)               // 32x132 f32 transpose buf
#define SMEM2      (TRANS_OFF + 32 * 132 * 4)
#define SMEM1      (STAGES * STAGE_BYTES)

// ---------------- scratch (static __device__, no allocations) ----------------
__device__ __half g_y[(size_t)MTOT * DIM];
__device__ __half g_h[(size_t)MTOT * IDIM];
__device__ __half g_w1h[(size_t)IDIM * DIM];
__device__ __half g_w2h[(size_t)DIM * IDIM];
__device__ float  g_part[BATCH * IDIM];
__device__ __half g_scale[BATCH * IDIM];
__device__ float  g_gw2[DIM];

// =============================================================================
// helpers
// =============================================================================
__device__ __forceinline__ float gelu_fast(float v) {
    const float x  = v * 0.70710678118654752f;
    const float ax = fabsf(x);
    const float t  = __fdividef(1.0f, fmaf(0.3275911f, ax, 1.0f));
    float p = fmaf(t, 1.061405429f, -1.453152027f);
    p = fmaf(t, p, 1.421413741f);
    p = fmaf(t, p, -0.284496736f);
    p = fmaf(t, p, 0.254829592f);
    p *= t;
    const float e = __expf(-x * x);
    float erfv = fmaf(-p, e, 1.0f);
    erfv = copysignf(erfv, x);
    return 0.5f * v * (1.0f + erfv);
}
__device__ __forceinline__ uint32_t smem_u32(const void* p) {
    uint32_t a;
    asm("{ .reg .u64 t; cvta.to.shared.u64 t, %1; cvt.u32.u64 %0, t; }"
        : "=r"(a) : "l"(p));
    return a;
}
__device__ __forceinline__ void cp_async16(uint32_t dst, const void* src) {
    asm volatile("cp.async.cg.shared.global [%0], [%1], 16;" :: "r"(dst), "l"(src));
}
#define CP_COMMIT() asm volatile("cp.async.commit_group;" ::: "memory")
#define CP_WAIT(n)  asm volatile("cp.async.wait_group %0;" :: "n"(n) : "memory")

__device__ __forceinline__ void ldsm_x4(uint32_t* d, uint32_t addr) {
    asm volatile("ldmatrix.sync.aligned.m8n8.x4.shared.b16 {%0,%1,%2,%3}, [%4];"
                 : "=r"(d[0]), "=r"(d[1]), "=r"(d[2]), "=r"(d[3]) : "r"(addr));
}
__device__ __forceinline__ uint32_t lds_u32(uint32_t a) {
    uint32_t v;
    asm volatile("ld.shared.b32 %0, [%1];" : "=r"(v) : "r"(a));
    return v;
}
__device__ __forceinline__ uint32_t hmul2(uint32_t a, uint32_t s) {
    uint32_t o;
    asm("mul.rn.f16x2 %0, %1, %2;" : "=r"(o) : "r"(a), "r"(s));
    return o;
}
__device__ __forceinline__ void mma_f16(float* c, const uint32_t* a, const uint32_t* b) {
    asm volatile(
        "mma.sync.aligned.m16n8k16.row.col.f32.f16.f16.f32 "
        "{%0,%1,%2,%3}, {%4,%5,%6,%7}, {%8,%9}, {%0,%1,%2,%3};"
        : "+f"(c[0]), "+f"(c[1]), "+f"(c[2]), "+f"(c[3])
        : "r"(a[0]), "r"(a[1]), "r"(a[2]), "r"(a[3]), "r"(b[0]), "r"(b[1]));
}

__device__ __forceinline__ void issue_stage(
    uint32_t sb, int st, const __half* Ag, const __half* Bg, int kt, int tid, int K)
{
    const uint32_t base = sb + st * STAGE_BYTES;
    #pragma unroll
    for (int q = 0; q < 2; q++) {
        const int cid = tid + q * 256;
        const int r = cid >> 2, c = cid & 3;
        const uint32_t so = (uint32_t)(r * 64 + ((c ^ ((r >> 1) & 3)) << 4));
        cp_async16(base + so,        Ag + (size_t)r * K + kt * BK + c * 8);
        cp_async16(base + 8192 + so, Bg + (size_t)r * K + kt * BK + c * 8);
    }
}

template<bool SCALE>
__device__ __forceinline__ void compute_kiter(
    uint32_t abase, uint32_t bbase,
    uint32_t offA0, const uint32_t* cswA,
    uint32_t offB0, const uint32_t* cswB,
    uint32_t s_addr, float acc[2][8][4])
{
    #pragma unroll
    for (int ks = 0; ks < 2; ks++) {
        uint32_t af[2][4];
        ldsm_x4(af[0], abase + offA0 + cswA[ks]);
        ldsm_x4(af[1], abase + offA0 + 1024 + cswA[ks]);
        if (SCALE) {
            const uint32_t slo = lds_u32(s_addr + ks * 32);
            const uint32_t shi = lds_u32(s_addr + ks * 32 + 16);
            #pragma unroll
            for (int mi = 0; mi < 2; mi++) {
                af[mi][0] = hmul2(af[mi][0], slo);
                af[mi][1] = hmul2(af[mi][1], slo);
                af[mi][2] = hmul2(af[mi][2], shi);
                af[mi][3] = hmul2(af[mi][3], shi);
            }
        }
        uint32_t bf[4][4];
        #pragma unroll
        for (int q = 0; q < 4; q++)
            ldsm_x4(bf[q], bbase + offB0 + q * 1024 + cswB[ks]);
        #pragma unroll
        for (int mi = 0; mi < 2; mi++)
            #pragma unroll
            for (int j = 0; j < 8; j++)
                mma_f16(acc[mi][j], af[mi], &bf[j >> 1][(j & 1) * 2]);
    }
}

struct FragAddr {
    uint32_t offA0, offB0;
    uint32_t cswA[2], cswB[2];
};
__device__ __forceinline__ FragAddr make_frag_addr(int warp, int lane) {
    FragAddr fa;
    const int wm = warp & 3, wn = warp >> 2;
    const int mi4 = lane >> 3, rloc = lane & 7;
    const int rowA = wm * 32 + (mi4 & 1) * 8 + rloc;
    fa.offA0 = rowA * 64;
    const uint32_t rmA = (rowA >> 1) & 3;
    const uint32_t chA = (uint32_t)(mi4 >> 1);
    fa.cswA[0] = ((0 + chA) ^ rmA) << 4;
    fa.cswA[1] = ((2 + chA) ^ rmA) << 4;
    const int rowB = wn * 64 + (mi4 >> 1) * 8 + rloc;
    fa.offB0 = rowB * 64;
    const uint32_t rmB = (rowB >> 1) & 3;
    const uint32_t chB = (uint32_t)(mi4 & 1);
    fa.cswB[0] = ((0 + chB) ^ rmB) << 4;
    fa.cswB[1] = ((2 + chB) ^ rmB) << 4;
    return fa;
}

// =============================================================================
// pre: blocks 0..767 weight-halve + zero g_part; 768..831 gw2;
//      832..2879 conv(K=7)+LN with vectorized x loads.
// =============================================================================
__global__ __launch_bounds__(256) void pre_kernel(
    const float* __restrict__ x, const float* __restrict__ dw_w,
    const float* __restrict__ dw_b, const float* __restrict__ ln_g,
    const float* __restrict__ ln_b, const float* __restrict__ w1,
    const float* __restrict__ w2, const float* __restrict__ grn_b)
{
    __shared__ float sy[DIM][17];
    const int bid = blockIdx.x;
    const int tid = threadIdx.x;

    if (bid < 768) {
        const int i = bid * 256 + tid;
        {
            const float4 v = *(const float4*)(w1 + (size_t)i * 4);
            *(__half2*)(g_w1h + (size_t)i * 4)     = __floats2half2_rn(v.x, v.y);
            *(__half2*)(g_w1h + (size_t)i * 4 + 2) = __floats2half2_rn(v.z, v.w);
        }
        {
            const float4 v = *(const float4*)(w2 + (size_t)i * 4);
            *(__half2*)(g_w2h + (size_t)i * 4)     = __floats2half2_rn(v.x, v.y);
            *(__half2*)(g_w2h + (size_t)i * 4 + 2) = __floats2half2_rn(v.z, v.w);
        }
        if (i < BATCH * IDIM / 4)
            *(float4*)(g_part + (size_t)i * 4) = make_float4(0.f, 0.f, 0.f, 0.f);
        return;
    }
    if (bid < 832) {
        // gw2[c] = grn_b . w2[c,:]  (float w2 — independent of halving)
        const int w = (bid - 768) * 8 + (tid >> 5);
        const int lane = tid & 31;
        const float* row = w2 + (size_t)w * IDIM;
        float s = 0.f;
        for (int i = lane; i < IDIM; i += 32) s += row[i] * grn_b[i];
        #pragma unroll
        for (int o = 16; o; o >>= 1) s += __shfl_xor_sync(0xffffffffu, s, o);
        if (lane == 0) g_gw2[w] = s;
        return;
    }

    // ---- conv + LN ----
    const int cb = bid - 832;
    const int b  = cb >> 7;
    const int t0 = (cb & 127) * 16;
    // vectorized path needs [t0-4, t0+24) in range
    const bool interior = (t0 >= 4) && (t0 + 24 <= TLEN);

    #pragma unroll
    for (int it = 0; it < 8; it++) {
        const int idx = tid + it * 256;     // 0..2047
        const int c = idx >> 2, tq = idx & 3;
        const int tb  = t0 + tq * 4 - 3;    // first x index needed
        const int tb4 = t0 + tq * 4 - 4;    // 16B-aligned vector base
        const float* xrow = x + ((size_t)b * DIM + c) * TLEN;
        float xv[16];
        if (interior) {
            #pragma unroll
            for (int q = 0; q < 4; q++)
                *(float4*)&xv[q * 4] = *(const float4*)(xrow + tb4 + q * 4);
        } else {
            #pragma unroll
            for (int j = 0; j < 16; j++) {
                const int t = tb4 + j;
                xv[j] = (t >= 0 && t < TLEN) ? xrow[t] : 0.f;
            }
        }
        // element k of the conv window is xv[1 + k + out_offset]
        const float* wc = dw_w + c * 7;
        const float bv = dw_b[c];
        float o0 = bv, o1 = bv, o2 = bv, o3 = bv;
        #pragma unroll
        for (int k = 0; k < 7; k++) {
            const float w = wc[k];
            o0 = fmaf(xv[1 + k],     w, o0);
            o1 = fmaf(xv[1 + k + 1], w, o1);
            o2 = fmaf(xv[1 + k + 2], w, o2);
            o3 = fmaf(xv[1 + k + 3], w, o3);
        }
        (void)tb;
        sy[c][tq * 4 + 0] = o0;
        sy[c][tq * 4 + 1] = o1;
        sy[c][tq * 4 + 2] = o2;
        sy[c][tq * 4 + 3] = o3;
    }
    __syncthreads();

    const int wid = tid >> 5, lane = tid & 31;
    #pragma unroll
    for (int rr = 0; rr < 2; rr++) {
        const int tl = wid + rr * 8;
        float sum = 0.f, sq = 0.f;
        #pragma unroll
        for (int c = lane; c < DIM; c += 32) {
            const float v = sy[c][tl];
            sum += v; sq += v * v;
        }
        #pragma unroll
        for (int o = 16; o; o >>= 1) {
            sum += __shfl_xor_sync(0xffffffffu, sum, o);
            sq  += __shfl_xor_sync(0xffffffffu, sq,  o);
        }
        const float mu  = sum * (1.f / DIM);
        const float var = sq * (1.f / DIM) - mu * mu;
        const float rs  = rsqrtf(var + 1e-6f);
        __half* yr = g_y + ((size_t)b * TLEN + (t0 + tl)) * DIM;
        for (int c = lane; c < DIM; c += 32)
            yr[c] = __float2half_rn((sy[c][tl] - mu) * rs * ln_g[c] + ln_b[c]);
    }
}

// =============================================================================
// GEMM1 (persistent, continuous pipeline): h = gelu(y @ w1^T + b1) + GRN sumsq
// =============================================================================
__global__ void __launch_bounds__(256, 2) gemm1_kernel(const float* __restrict__ b1)
{
    extern __shared__ char smem[];
    const uint32_t sb = smem_u32(smem);
    const int tid = threadIdx.x;
    const int warp = tid >> 5, lane = tid & 31;
    const int wm = warp & 3, wn = warp >> 2;
    const FragAddr fa = make_frag_addr(warp, lane);
    const int NKT = DIM / BK;                     // 16
    const int NT  = (IDIM / 128) * (MTOT / 128);  // 3072
    const int ntile = (NT - (int)blockIdx.x + (int)gridDim.x - 1) / (int)gridDim.x;
    if (ntile <= 0) return;
    const int total = ntile * NKT;

    int pt = 0, pk = 0;
    const __half *Ap = g_y   + (size_t)(((int)blockIdx.x / 12) * 128) * DIM;
    const __half *Bp = g_w1h + (size_t)(((int)blockIdx.x % 12) * 128) * DIM;

    #pragma unroll
    for (int s = 0; s < STAGES - 1; s++) {
        if (s < total) {
            issue_stage(sb, s & 3, Ap, Bp, pk, tid, DIM);
            if (++pk == NKT) {
                pk = 0; pt++;
                if (pt < ntile) {
                    const int t = (int)blockIdx.x + pt * (int)gridDim.x;
                    Ap = g_y + (size_t)((t / 12) * 128) * DIM;
                    Bp = g_w1h + (size_t)((t % 12) * 128) * DIM;
                }
            }
        }
        CP_COMMIT();
    }

    int ct = 0, kt = 0;
    int m0 = ((int)blockIdx.x / 12) * 128, n0 = ((int)blockIdx.x % 12) * 128;
    float acc[2][8][4] = {};
    const int r4 = lane >> 2, c4 = lane & 3;

    for (int g = 0; g < total; g++) {
        CP_WAIT(STAGES - 2);
        __syncthreads();
        if (g + STAGES - 1 < total) {
            issue_stage(sb, (g + STAGES - 1) & 3, Ap, Bp, pk, tid, DIM);
            if (++pk == NKT) {
                pk = 0; pt++;
                if (pt < ntile) {
                    const int t = (int)blockIdx.x + pt * (int)gridDim.x;
                    Ap = g_y + (size_t)((t / 12) * 128) * DIM;
                    Bp = g_w1h + (size_t)((t % 12) * 128) * DIM;
                }
            }
        }
        CP_COMMIT();
        const uint32_t abase = sb + (g & 3) * STAGE_BYTES;
        compute_kiter<false>(abase, abase + 8192, fa.offA0, fa.cswA, fa.offB0, fa.cswB, 0, acc);

        if (++kt == NKT) {
            kt = 0;
            #pragma unroll
            for (int mi = 0; mi < 2; mi++) {
                #pragma unroll
                for (int j = 0; j < 8; j++) {
                    const int n = n0 + wn * 64 + j * 8 + c4 * 2;
                    const float bv0 = b1[n], bv1 = b1[n + 1];
                    acc[mi][j][0] = __half2float(__float2half_rn(gelu_fast(acc[mi][j][0] + bv0)));
                    acc[mi][j][1] = __half2float(__float2half_rn(gelu_fast(acc[mi][j][1] + bv1)));
                    acc[mi][j][2] = __half2float(__float2half_rn(gelu_fast(acc[mi][j][2] + bv0)));
                    acc[mi][j][3] = __half2float(__float2half_rn(gelu_fast(acc[mi][j][3] + bv1)));
                }
            }
            #pragma unroll
            for (int mi = 0; mi < 2; mi++) {
                const int m = m0 + wm * 32 + mi * 16 + r4;
                #pragma unroll
                for (int j = 0; j < 8; j++) {
                    const int n = n0 + wn * 64 + j * 8 + c4 * 2;
                    *(__half2*)(g_h + (size_t)m * IDIM + n) =
                        __floats2half2_rn(acc[mi][j][0], acc[mi][j][1]);
                    *(__half2*)(g_h + (size_t)(m + 8) * IDIM + n) =
                        __floats2half2_rn(acc[mi][j][2], acc[mi][j][3]);
                }
            }
            const int b = m0 >> 11;
            #pragma unroll
            for (int j = 0; j < 8; j++) {
                float s0 = acc[0][j][0] * acc[0][j][0] + acc[0][j][2] * acc[0][j][2]
                         + acc[1][j][0] * acc[1][j][0] + acc[1][j][2] * acc[1][j][2];
                float s1 = acc[0][j][1] * acc[0][j][1] + acc[0][j][3] * acc[0][j][3]
                         + acc[1][j][1] * acc[1][j][1] + acc[1][j][3] * acc[1][j][3];
                #pragma unroll
                for (int o = 4; o < 32; o <<= 1) {
                    s0 += __shfl_xor_sync(0xffffffffu, s0, o);
                    s1 += __shfl_xor_sync(0xffffffffu, s1, o);
                }
                if (lane < 4) {
                    const int n = n0 + wn * 64 + j * 8 + lane * 2;
                    atomicAdd(&g_part[b * IDIM + n],     s0);
                    atomicAdd(&g_part[b * IDIM + n + 1], s1);
                }
            }
            #pragma unroll
            for (int mi = 0; mi < 2; mi++)
                #pragma unroll
                for (int j = 0; j < 8; j++)
                    #pragma unroll
                    for (int q = 0; q < 4; q++) acc[mi][j][q] = 0.f;
            if (++ct < ntile) {
                const int t = (int)blockIdx.x + ct * (int)gridDim.x;
                m0 = (t / 12) * 128; n0 = (t % 12) * 128;
            }
        }
    }
}

// =============================================================================
// GRN scale (16 blocks)
// =============================================================================
__global__ __launch_bounds__(256) void grn_scale_kernel(const float* __restrict__ grn_g)
{
    __shared__ float sgx[IDIM];
    __shared__ float red[256];
    const int b = blockIdx.x;
    const int tid = threadIdx.x;
    float local = 0.f;
    for (int i = tid; i < IDIM; i += 256) {
        const float gx = sqrtf(g_part[b * IDIM + i]);
        sgx[i] = gx;
        local += gx;
    }
    red[tid] = local;
    __syncthreads();
    for (int o = 128; o; o >>= 1) {
        if (tid < o) red[tid] += red[tid + o];
        __syncthreads();
    }
    const float mean = red[0] * (1.f / IDIM);
    const float inv  = 1.f / (mean + 1e-6f);
    for (int i = tid; i < IDIM; i += 256)
        g_scale[b * IDIM + i] = __float2half_rn(grn_g[i] * sgx[i] * inv + 1.0f);
}

// =============================================================================
// GEMM2 (persistent, continuous pipeline): out = x + T((h*scale) @ w2^T + gw2 + b2)
// =============================================================================
__global__ void __launch_bounds__(256, 2) gemm2_kernel(
    const float* __restrict__ b2v, const float* __restrict__ xres,
    float* __restrict__ out)
{
    extern __shared__ char smem[];
    const uint32_t sb = smem_u32(smem);
    const int tid = threadIdx.x;
    const int warp = tid >> 5, lane = tid & 31;
    const int wm = warp & 3, wn = warp >> 2;
    const FragAddr fa = make_frag_addr(warp, lane);
    const int NKT = IDIM / BK;                   // 48
    const int NT  = (DIM / 128) * (MTOT / 128);  // 1024
    const int ntile = (NT - (int)blockIdx.x + (int)gridDim.x - 1) / (int)gridDim.x;
    if (ntile <= 0) return;
    const int total = ntile * NKT;

    int pt = 0, pk = 0;
    const __half *Ap, *Bp;
    {
        const int t = (int)blockIdx.x;
        Ap = g_h   + (size_t)((t / 4) * 128) * IDIM;
        Bp = g_w2h + (size_t)((t % 4) * 128) * IDIM;
    }
    #pragma unroll
    for (int s = 0; s < STAGES - 1; s++) {
        if (s < total) {
            if (pk == 0 && tid < 192) {
                const int t = (int)blockIdx.x + pt * (int)gridDim.x;
                const int bbp = ((t / 4) * 128) >> 11;
                cp_async16(sb + SC_OFF + (pt & 1) * 3072 + tid * 16,
                           g_scale + (size_t)bbp * IDIM + tid * 8);
            }
            issue_stage(sb, s & 3, Ap, Bp, pk, tid, IDIM);
            if (++pk == NKT) {
                pk = 0; pt++;
                if (pt < ntile) {
                    const int t = (int)blockIdx.x + pt * (int)gridDim.x;
                    Ap = g_h + (size_t)((t / 4) * 128) * IDIM;
                    Bp = g_w2h + (size_t)((t % 4) * 128) * IDIM;
                }
            }
        }
        CP_COMMIT();
    }

    int ct = 0, kt = 0;
    int m0 = (((int)blockIdx.x) / 4) * 128, n0 = (((int)blockIdx.x) % 4) * 128;
    float acc[2][8][4] = {};
    const int r4 = lane >> 2, c4 = lane & 3;

    for (int g = 0; g < total; g++) {
        CP_WAIT(STAGES - 2);
        __syncthreads();
        if (g + STAGES - 1 < total) {
            if (pk == 0 && tid < 192) {
                const int t = (int)blockIdx.x + pt * (int)gridDim.x;
                const int bbp = ((t / 4) * 128) >> 11;
                cp_async16(sb + SC_OFF + (pt & 1) * 3072 + tid * 16,
                           g_scale + (size_t)bbp * IDIM + tid * 8);
            }
            issue_stage(sb, (g + STAGES - 1) & 3, Ap, Bp, pk, tid, IDIM);
            if (++pk == NKT) {
                pk = 0; pt++;
                if (pt < ntile) {
                    const int t = (int)blockIdx.x + pt * (int)gridDim.x;
                    Ap = g_h + (size_t)((t / 4) * 128) * IDIM;
                    Bp = g_w2h + (size_t)((t % 4) * 128) * IDIM;
                }
            }
        }
        CP_COMMIT();
        const uint32_t abase = sb + (g & 3) * STAGE_BYTES;
        const uint32_t s_addr = sb + SC_OFF + (ct & 1) * 3072 + kt * 64 + c4 * 4;
        compute_kiter<true>(abase, abase + 8192, fa.offA0, fa.cswA, fa.offB0, fa.cswB, s_addr, acc);

        if (++kt == NKT) {
            kt = 0;
            const int bb = m0 >> 11;
            const int t0 = m0 & (TLEN - 1);
            float (*trans)[132] = (float(*)[132])(smem + TRANS_OFF);
            __syncthreads();
            #pragma unroll
            for (int q = 0; q < 4; q++) {
                if (wn == (q >> 1)) {
                    const int jb = (q & 1) * 4;
                    #pragma unroll
                    for (int jl = 0; jl < 4; jl++) {
                        const int cl = (jb + jl) * 8 + c4 * 2 - (q & 1) * 32;
                        #pragma unroll
                        for (int mi = 0; mi < 2; mi++) {
                            const int ml = wm * 32 + mi * 16 + r4;
                            trans[cl][ml]         = acc[mi][jb + jl][0];
                            trans[cl + 1][ml]     = acc[mi][jb + jl][1];
                            trans[cl][ml + 8]     = acc[mi][jb + jl][2];
                            trans[cl + 1][ml + 8] = acc[mi][jb + jl][3];
                        }
                    }
                }
                __syncthreads();
                for (int r = tid; r < 32 * 128; r += 256) {
                    const int cl = r >> 7, tl = r & 127;
                    const int c = n0 + 32 * q + cl;
                    const size_t oi = ((size_t)(bb * DIM + c)) * TLEN + t0 + tl;
                    out[oi] = xres[oi] + trans[cl][tl] + b2v[c] + g_gw2[c];
                }
                __syncthreads();
            }
            #pragma unroll
            for (int mi = 0; mi < 2; mi++)
                #pragma unroll
                for (int j = 0; j < 8; j++)
                    #pragma unroll
                    for (int q = 0; q < 4; q++) acc[mi][j][q] = 0.f;
            if (++ct < ntile) {
                const int t = (int)blockIdx.x + ct * (int)gridDim.x;
                m0 = (t / 4) * 128; n0 = (t % 4) * 128;
            }
        }
    }
}

// =============================================================================
// Launch
// =============================================================================
extern "C" void kernel_launch(void* const* d_in, const int* in_sizes, int n_in,
                              void* d_out, int out_size)
{
    const float* x     = (const float*)d_in[0];
    const float* dw_w  = (const float*)d_in[1];
    const float* dw_b  = (const float*)d_in[2];
    const float* ln_g  = (const float*)d_in[3];
    const float* ln_b  = (const float*)d_in[4];
    const float* w1    = (const float*)d_in[5];
    const float* b1    = (const float*)d_in[6];
    const float* grn_g = (const float*)d_in[7];
    const float* grn_b = (const float*)d_in[8];
    const float* w2    = (const float*)d_in[9];
    const float* b2    = (const float*)d_in[10];
    float* out = (float*)d_out;

    cudaFuncSetAttribute(gemm1_kernel, cudaFuncAttributeMaxDynamicSharedMemorySize, SMEM1);
    cudaFuncSetAttribute(gemm2_kernel, cudaFuncAttributeMaxDynamicSharedMemorySize, SMEM2);

    pre_kernel<<<2880, 256>>>(x, dw_w, dw_b, ln_g, ln_b, w1, w2, grn_b);
    gemm1_kernel<<<PGRID, 256, SMEM1>>>(b1);
    grn_scale_kernel<<<16, 256>>>(grn_g);
    gemm2_kernel<<<PGRID, 256, SMEM2>>>(b2, x, out);
}